// round 14
// baseline (speedup 1.0000x reference)
#include <cuda_runtime.h>
#include <cuda_bf16.h>
#include <math.h>
#include <stdint.h>

// ---------------- problem dims ----------------
#define LAY 12
#define NH  12
#define Dm  768
#define HD  64
#define NTOK 512
#define BAT  4
#define MTOK (BAT*NTOK)     // 2048
#define KP   16384          // C*P^3
#define D4   3072
#define QKVN 2304
#define PSPLIT 4
#define MSPLIT 2

// ---------------- scratch (device globals; no allocs allowed) ----------------
__device__ __nv_bfloat16 g_patch_h[(size_t)MTOK * KP];
__device__ __nv_bfloat16 g_patch_l[(size_t)MTOK * KP];
__device__ __nv_bfloat16 g_wp_h[(size_t)Dm * KP];
__device__ __nv_bfloat16 g_wp_l[(size_t)Dm * KP];
__device__ __nv_bfloat16 g_wqkv_h[(size_t)LAY * QKVN * Dm];
__device__ __nv_bfloat16 g_wqkv_l[(size_t)LAY * QKVN * Dm];
__device__ __nv_bfloat16 g_w1_h[(size_t)LAY * D4 * Dm];   // [l][3072][768]
__device__ __nv_bfloat16 g_w1_l[(size_t)LAY * D4 * Dm];
__device__ __nv_bfloat16 g_w2_h[(size_t)LAY * Dm * D4];   // [l][768][3072]
__device__ __nv_bfloat16 g_w2_l[(size_t)LAY * Dm * D4];
__device__ float g_bqkv[(size_t)LAY * QKVN];
__device__ float g_h[(size_t)MTOK * Dm];
__device__ __nv_bfloat16 g_y_h[(size_t)MTOK * Dm];
__device__ __nv_bfloat16 g_y_l[(size_t)MTOK * Dm];
__device__ float g_qkv[(size_t)MTOK * QKVN];
__device__ float g_S[(size_t)BAT * NH * NTOK * NTOK];
__device__ __nv_bfloat16 g_m1_h[(size_t)MTOK * D4];
__device__ __nv_bfloat16 g_m1_l[(size_t)MTOK * D4];
__device__ float g_split[(size_t)PSPLIT * MTOK * Dm];

// ---------------- helpers ----------------
__device__ __forceinline__ float gelu_f(float v) {
    float c = 0.7978845608028654f * (v + 0.044715f * v * v * v);
    return 0.5f * v * (1.0f + tanhf(c));
}
__device__ __forceinline__ void split2(float v, __nv_bfloat16* hi, __nv_bfloat16* lo) {
    __nv_bfloat16 h = __float2bfloat16(v);
    *hi = h;
    *lo = __float2bfloat16(v - __bfloat162float(h));
}
__device__ __forceinline__ uint32_t smem_u32(const void* p) {
    uint32_t a;
    asm("{ .reg .u64 t; cvta.to.shared.u64 t, %1; cvt.u32.u64 %0, t; }" : "=r"(a) : "l"(p));
    return a;
}
#define SWZ(o) ((o) ^ ((((unsigned)(o)) >> 3) & 0x70u))

__device__ __forceinline__ void cpasync16(uint32_t dst, const void* src) {
    asm volatile("cp.async.cg.shared.global [%0], [%1], 16;" :: "r"(dst), "l"(src) : "memory");
}
#define LDSM4(r, addr) \
    asm volatile("ldmatrix.sync.aligned.m8n8.x4.shared.b16 {%0,%1,%2,%3}, [%4];" \
        : "=r"((r)[0]),"=r"((r)[1]),"=r"((r)[2]),"=r"((r)[3]) : "r"(addr))
#define MMA16816(c, a, b0, b1) \
    asm volatile("mma.sync.aligned.m16n8k16.row.col.f32.bf16.bf16.f32 " \
        "{%0,%1,%2,%3}, {%4,%5,%6,%7}, {%8,%9}, {%0,%1,%2,%3};" \
        : "+f"((c)[0]),"+f"((c)[1]),"+f"((c)[2]),"+f"((c)[3]) \
        : "r"((a)[0]),"r"((a)[1]),"r"((a)[2]),"r"((a)[3]), "r"(b0),"r"(b1))

#define GEMM_SMEM (2 * 65536)

// ============ mma.sync bf16x3 GEMM: C[M,N] = (Ah+Al)[M,K] x (Bh+Bl)[N,K]^T ============
// CTA tile 128x128, Kstep 64, 2-stage cp.async pipeline, 8 warps (2x4), warp tile 64x32.
// MODE 0: C = acc + bias     MODE 2: split(gelu(acc+bias)) -> oh/ol     MODE 4: split-K raw partial
template<int MODE>
__global__ void __launch_bounds__(256, 1) gemm_mma(
    const __nv_bfloat16* __restrict__ Ah, const __nv_bfloat16* __restrict__ Al,
    const __nv_bfloat16* __restrict__ Bh, const __nv_bfloat16* __restrict__ Bl,
    int lda, int Klen, int M,
    float* __restrict__ C, int ldc, const float* __restrict__ bias,
    __nv_bfloat16* __restrict__ oh, __nv_bfloat16* __restrict__ ol)
{
    extern __shared__ char smem[];
    uint32_t sb = smem_u32(smem);
    int tid = threadIdx.x;
    int bm = blockIdx.y << 7, bn = blockIdx.x << 7;
    if (MODE == 4) {
        long ko = (long)blockIdx.z * Klen;
        Ah += ko; Al += ko; Bh += ko; Bl += ko;
        C += (long)blockIdx.z * (long)M * ldc;
    }

    const int nsteps = Klen >> 6;

    auto loadstep = [&](int s) {
        uint32_t buf = sb + (uint32_t)(s & 1) * 65536u;
        long k0 = (long)s << 6;
#pragma unroll
        for (int i = 0; i < 16; i++) {
            int t = tid + (i << 8);
            int which = t >> 10;          // 0:Ah 1:Al 2:Bh 3:Bl
            int r = (t >> 3) & 127;
            int c16 = t & 7;
            const __nv_bfloat16* src;
            if (which == 0)      src = Ah + (long)(bm + r) * lda + k0 + c16 * 8;
            else if (which == 1) src = Al + (long)(bm + r) * lda + k0 + c16 * 8;
            else if (which == 2) src = Bh + (long)(bn + r) * lda + k0 + c16 * 8;
            else                 src = Bl + (long)(bn + r) * lda + k0 + c16 * 8;
            cpasync16(buf + (uint32_t)which * 16384u + SWZ(r * 128 + c16 * 16), src);
        }
        asm volatile("cp.async.commit_group;" ::: "memory");
    };

    loadstep(0);
    loadstep(1);

    int wid = tid >> 5, l = tid & 31;
    int wm = wid >> 2, wn = wid & 3;          // 2 x 4 warps

    // per-lane ldmatrix offsets (within 16KB tile, before swizzle)
    int aOff0 = (wm * 64 + (l & 15)) * 128 + ((l >> 4) << 4);          // + mf*2048 + k16*32
    int bOff0 = (wn * 32 + ((l >> 4) << 3) + (l & 7)) * 128 + (((l >> 3) & 1) << 4); // + nfp*2048 + k16*32

    float acc[4][4][4];
#pragma unroll
    for (int a = 0; a < 4; a++)
#pragma unroll
        for (int b = 0; b < 4; b++)
#pragma unroll
            for (int c = 0; c < 4; c++) acc[a][b][c] = 0.f;

    for (int s = 0; s < nsteps; s++) {
        if (s + 1 < nsteps) asm volatile("cp.async.wait_group 1;" ::: "memory");
        else                asm volatile("cp.async.wait_group 0;" ::: "memory");
        __syncthreads();
        uint32_t buf = sb + (uint32_t)(s & 1) * 65536u;
#pragma unroll
        for (int k16 = 0; k16 < 4; k16++) {
            uint32_t ah[4][4], al[4][4], bb[2][4];
            int kb = k16 << 5;
#pragma unroll
            for (int mf = 0; mf < 4; mf++) {
                int o = aOff0 + mf * 2048 + kb;
                LDSM4(ah[mf], buf + SWZ(o));
                LDSM4(al[mf], buf + 16384u + SWZ(o));
            }
#pragma unroll
            for (int p = 0; p < 2; p++)
                LDSM4(bb[p], buf + 32768u + SWZ(bOff0 + p * 2048 + kb));
#pragma unroll
            for (int mf = 0; mf < 4; mf++)
#pragma unroll
                for (int nf = 0; nf < 4; nf++) {
                    MMA16816(acc[mf][nf], ah[mf], bb[nf >> 1][(nf & 1) * 2], bb[nf >> 1][(nf & 1) * 2 + 1]);
                    MMA16816(acc[mf][nf], al[mf], bb[nf >> 1][(nf & 1) * 2], bb[nf >> 1][(nf & 1) * 2 + 1]);
                }
#pragma unroll
            for (int p = 0; p < 2; p++)
                LDSM4(bb[p], buf + 49152u + SWZ(bOff0 + p * 2048 + kb));
#pragma unroll
            for (int mf = 0; mf < 4; mf++)
#pragma unroll
                for (int nf = 0; nf < 4; nf++)
                    MMA16816(acc[mf][nf], ah[mf], bb[nf >> 1][(nf & 1) * 2], bb[nf >> 1][(nf & 1) * 2 + 1]);
        }
        __syncthreads();
        if (s + 2 < nsteps) loadstep(s + 2);
    }

    // ---------------- epilogue: direct register -> gmem ----------------
#pragma unroll
    for (int mf = 0; mf < 4; mf++)
#pragma unroll
        for (int nf = 0; nf < 4; nf++) {
            int gr = bm + wm * 64 + mf * 16 + (l >> 2);
            int gc = bn + wn * 32 + nf * 8 + (l & 3) * 2;
#pragma unroll
            for (int hrow = 0; hrow < 2; hrow++) {
                long go = (long)(gr + hrow * 8) * ldc + gc;
                float v0 = acc[mf][nf][hrow * 2 + 0];
                float v1 = acc[mf][nf][hrow * 2 + 1];
                if (MODE == 0) {
                    float2 r; r.x = v0 + bias[gc]; r.y = v1 + bias[gc + 1];
                    *reinterpret_cast<float2*>(C + go) = r;
                } else if (MODE == 2) {
                    float a0 = gelu_f(v0 + bias[gc]);
                    float a1 = gelu_f(v1 + bias[gc + 1]);
                    __nv_bfloat16 h0, l0, h1, l1;
                    split2(a0, &h0, &l0); split2(a1, &h1, &l1);
                    __nv_bfloat162 rh; rh.x = h0; rh.y = h1;
                    __nv_bfloat162 rl; rl.x = l0; rl.y = l1;
                    *reinterpret_cast<__nv_bfloat162*>(oh + go) = rh;
                    *reinterpret_cast<__nv_bfloat162*>(ol + go) = rl;
                } else {
                    float2 r; r.x = v0; r.y = v1;
                    *reinterpret_cast<float2*>(C + go) = r;
                }
            }
        }
}

// ---------------- combine kernels (split-K reductions + epilogues) ----------------
__global__ void __launch_bounds__(256) combine_patch(
    const float* __restrict__ parts, const float* __restrict__ bp,
    const float* __restrict__ pos, float* __restrict__ h) {
    long i = (long)blockIdx.x * 256 + threadIdx.x;
    if (i >= (long)MTOK * Dm) return;
    float s = 0.f;
#pragma unroll
    for (int z = 0; z < PSPLIT; z++) s += parts[(long)z * MTOK * Dm + i];
    int col = (int)(i % Dm);
    int n = (int)((i / Dm) & 511);
    h[i] = s + bp[col] + pos[(long)n * Dm + col];
}

__global__ void __launch_bounds__(256) combine_mlp2(
    const float* __restrict__ parts, const float* __restrict__ b2, float* __restrict__ h) {
    long i = (long)blockIdx.x * 256 + threadIdx.x;
    if (i >= (long)MTOK * Dm) return;
    h[i] += parts[i] + parts[(long)MTOK * Dm + i] + b2[i % Dm];
}

// ---------------- patch gather + split ----------------
__global__ void __launch_bounds__(256) patch_gather(const float* __restrict__ x) {
    long idx = (long)blockIdx.x * 256 + threadIdx.x;
    if (idx >= (long)MTOK * KP) return;
    int c = (int)(idx & (KP - 1));
    int m = (int)(idx >> 14);
    int b = m >> 9; int t = m & 511;
    int d = t >> 6, hh = (t >> 3) & 7, w = t & 7;
    int ch = c >> 12; int r = c & 4095;
    int i = r >> 8, j = (r >> 4) & 15, k = r & 15;
    long xi = ((((long)(b * 4 + ch) * 128 + (d * 16 + i)) * 128) + (hh * 16 + j)) * 128 + (w * 16 + k);
    split2(x[xi], &g_patch_h[idx], &g_patch_l[idx]);
}

__global__ void __launch_bounds__(256) split_wp(const float* __restrict__ wp) {
    long i = (long)blockIdx.x * 256 + threadIdx.x;
    if (i < (long)Dm * KP) split2(wp[i], &g_wp_h[i], &g_wp_l[i]);
}

// ---------------- qkv weight pack+transpose+split ----------------
__global__ void pack_qkv_split(const float* __restrict__ Wq, const float* __restrict__ Wk,
                               const float* __restrict__ Wv) {
    __shared__ float t[32][33];
    int z = blockIdx.z;
    int sel = z / (LAY * NH); int lh = z % (LAY * NH);
    int l = lh / NH, h = lh % NH;
    const float* W = (sel == 0) ? Wq : (sel == 1) ? Wk : Wv;
    const float* s = W + (((long)l * NH + h) * Dm) * HD;
    int d0 = blockIdx.y * 32, e0 = blockIdx.x * 32;
    t[threadIdx.y][threadIdx.x] = s[(long)(d0 + threadIdx.y) * HD + e0 + threadIdx.x];
    __syncthreads();
    int n = sel * Dm + h * HD + e0 + threadIdx.y;
    long o = ((long)l * QKVN + n) * Dm + d0 + threadIdx.x;
    split2(t[threadIdx.x][threadIdx.y], &g_wqkv_h[o], &g_wqkv_l[o]);
}
__global__ void __launch_bounds__(256) pack_bqkv(const float* __restrict__ bq,
                                                 const float* __restrict__ bk,
                                                 const float* __restrict__ bv) {
    int i = blockIdx.x * 256 + threadIdx.x;
    if (i >= LAY * QKVN) return;
    int l = i / QKVN, c = i % QKVN;
    int sel = c / Dm, cc = c % Dm;
    int h = cc >> 6, e = cc & 63;
    const float* b = (sel == 0) ? bq : (sel == 1) ? bk : bv;
    g_bqkv[i] = b[((long)l * NH + h) * HD + e];
}

// ---------------- generic transpose+split ----------------
__global__ void transpose_split(const float* __restrict__ src, __nv_bfloat16* __restrict__ dh,
                                __nv_bfloat16* __restrict__ dl, int R, int Cc) {
    __shared__ float t[32][33];
    int l = blockIdx.z;
    int r0 = blockIdx.y * 32, c0 = blockIdx.x * 32;
    const float* s = src + (long)l * R * Cc;
    t[threadIdx.y][threadIdx.x] = s[(long)(r0 + threadIdx.y) * Cc + c0 + threadIdx.x];
    __syncthreads();
    long o = (long)l * R * Cc + (long)(c0 + threadIdx.y) * R + r0 + threadIdx.x;
    split2(t[threadIdx.x][threadIdx.y], &dh[o], &dl[o]);
}

// ---------------- layernorm -> bf16 hi/lo ----------------
__global__ void __launch_bounds__(256) layernorm_split(
    const float* __restrict__ hin, __nv_bfloat16* __restrict__ yh, __nv_bfloat16* __restrict__ yl,
    const float* __restrict__ g, const float* __restrict__ b) {
    __shared__ float r1[8], r2[8];
    long base = (long)blockIdx.x * Dm;
    int t = threadIdx.x;
    float v0 = hin[base + t], v1 = hin[base + t + 256], v2 = hin[base + t + 512];
    float s = v0 + v1 + v2;
#pragma unroll
    for (int o = 16; o > 0; o >>= 1) s += __shfl_xor_sync(0xffffffffu, s, o);
    if ((t & 31) == 0) r1[t >> 5] = s;
    __syncthreads();
    float tot = r1[0] + r1[1] + r1[2] + r1[3] + r1[4] + r1[5] + r1[6] + r1[7];
    float mu = tot * (1.f / 768.f);
    float d0 = v0 - mu, d1 = v1 - mu, d2 = v2 - mu;
    float q = d0 * d0 + d1 * d1 + d2 * d2;
#pragma unroll
    for (int o = 16; o > 0; o >>= 1) q += __shfl_xor_sync(0xffffffffu, q, o);
    if ((t & 31) == 0) r2[t >> 5] = q;
    __syncthreads();
    float tot2 = r2[0] + r2[1] + r2[2] + r2[3] + r2[4] + r2[5] + r2[6] + r2[7];
    float inv = rsqrtf(tot2 * (1.f / 768.f) + 1e-5f);
    split2(d0 * inv * g[t]       + b[t],       &yh[base + t],       &yl[base + t]);
    split2(d1 * inv * g[t + 256] + b[t + 256], &yh[base + t + 256], &yl[base + t + 256]);
    split2(d2 * inv * g[t + 512] + b[t + 512], &yh[base + t + 512], &yl[base + t + 512]);
}

// ---------------- attention (fp32 SIMT) ----------------
__global__ void __launch_bounds__(256) attn_qk(const float* __restrict__ qkv, float* __restrict__ S) {
    __shared__ float qs[64][68];
    __shared__ float ks[64][68];
    int b = blockIdx.z, h = blockIdx.y;
    int mt = (blockIdx.x >> 3) * 64, nt = (blockIdx.x & 7) * 64;
    int tid = threadIdx.x;
    const float* qbase = qkv + (long)(b * 512 + mt) * QKVN + h * 64;
    const float* kbase = qkv + (long)(b * 512 + nt) * QKVN + 768 + h * 64;
#pragma unroll
    for (int s = 0; s < 4; s++) {
        int f = tid + 256 * s; int r = f >> 4; int c = (f & 15) * 4;
        *(float4*)&qs[r][c] = *(const float4*)(qbase + (long)r * QKVN + c);
        *(float4*)&ks[r][c] = *(const float4*)(kbase + (long)r * QKVN + c);
    }
    __syncthreads();
    int tx = tid & 15, ty = tid >> 4;
    float acc[4][4];
#pragma unroll
    for (int i = 0; i < 4; i++)
#pragma unroll
        for (int j = 0; j < 4; j++) acc[i][j] = 0.f;
#pragma unroll
    for (int e = 0; e < 64; e++) {
        float a[4], bb[4];
#pragma unroll
        for (int i = 0; i < 4; i++) a[i] = qs[ty * 4 + i][e];
#pragma unroll
        for (int j = 0; j < 4; j++) bb[j] = ks[tx * 4 + j][e];
#pragma unroll
        for (int i = 0; i < 4; i++)
#pragma unroll
            for (int j = 0; j < 4; j++) acc[i][j] = fmaf(a[i], bb[j], acc[i][j]);
    }
#pragma unroll
    for (int i = 0; i < 4; i++) {
        float4 r;
        r.x = acc[i][0] * 0.125f; r.y = acc[i][1] * 0.125f;
        r.z = acc[i][2] * 0.125f; r.w = acc[i][3] * 0.125f;
        *(float4*)(S + ((long)((b * NH + h) * 512 + mt + ty * 4 + i)) * 512 + nt + tx * 4) = r;
    }
}

__global__ void __launch_bounds__(128) softmax_k(float* __restrict__ S) {
    __shared__ float r1[4], r2[4];
    float* row = S + (long)blockIdx.x * 512;
    int t = threadIdx.x;
    float4 v = *(float4*)(row + t * 4);
    float mx = fmaxf(fmaxf(v.x, v.y), fmaxf(v.z, v.w));
#pragma unroll
    for (int o = 16; o > 0; o >>= 1) mx = fmaxf(mx, __shfl_xor_sync(0xffffffffu, mx, o));
    if ((t & 31) == 0) r1[t >> 5] = mx;
    __syncthreads();
    mx = fmaxf(fmaxf(r1[0], r1[1]), fmaxf(r1[2], r1[3]));
    v.x = __expf(v.x - mx); v.y = __expf(v.y - mx);
    v.z = __expf(v.z - mx); v.w = __expf(v.w - mx);
    float s = v.x + v.y + v.z + v.w;
#pragma unroll
    for (int o = 16; o > 0; o >>= 1) s += __shfl_xor_sync(0xffffffffu, s, o);
    if ((t & 31) == 0) r2[t >> 5] = s;
    __syncthreads();
    s = r2[0] + r2[1] + r2[2] + r2[3];
    float inv = 1.0f / s;
    v.x *= inv; v.y *= inv; v.z *= inv; v.w *= inv;
    *(float4*)(row + t * 4) = v;
}

__global__ void __launch_bounds__(256) attn_av(
    const float* __restrict__ S, const float* __restrict__ qkv, float* __restrict__ hio) {
    __shared__ float Ss[64][68];
    __shared__ float Vs[64][68];
    int b = blockIdx.z, h = blockIdx.y, mt = blockIdx.x * 64;
    int tid = threadIdx.x; int tx = tid & 15, ty = tid >> 4;
    const float* Sbase = S + ((long)(b * NH + h) * 512 + mt) * 512;
    const float* vbase = qkv + (long)(b * 512) * QKVN + 1536 + h * 64;
    float acc[4][4];
#pragma unroll
    for (int i = 0; i < 4; i++)
#pragma unroll
        for (int j = 0; j < 4; j++) acc[i][j] = 0.f;
    for (int k0 = 0; k0 < 512; k0 += 64) {
#pragma unroll
        for (int s = 0; s < 4; s++) {
            int f = tid + 256 * s; int r = f >> 4; int c = (f & 15) * 4;
            *(float4*)&Ss[r][c] = *(const float4*)(Sbase + (long)r * 512 + k0 + c);
            *(float4*)&Vs[r][c] = *(const float4*)(vbase + (long)(k0 + r) * QKVN + c);
        }
        __syncthreads();
#pragma unroll
        for (int kk = 0; kk < 64; kk++) {
            float a[4], bb[4];
#pragma unroll
            for (int i = 0; i < 4; i++) a[i] = Ss[ty * 4 + i][kk];
            *(float4*)&bb[0] = *(const float4*)&Vs[kk][tx * 4];
#pragma unroll
            for (int i = 0; i < 4; i++)
#pragma unroll
                for (int j = 0; j < 4; j++) acc[i][j] = fmaf(a[i], bb[j], acc[i][j]);
        }
        __syncthreads();
    }
#pragma unroll
    for (int i = 0; i < 4; i++) {
        long off = (long)(b * 512 + mt + ty * 4 + i) * Dm + h * 64 + tx * 4;
        float4 cur = *(float4*)(hio + off);
        cur.x += acc[i][0]; cur.y += acc[i][1];
        cur.z += acc[i][2]; cur.w += acc[i][3];
        *(float4*)(hio + off) = cur;
    }
}

__global__ void __launch_bounds__(256) copy_out(const float* __restrict__ hin, float* __restrict__ out) {
    long i = (long)blockIdx.x * 256 + threadIdx.x;
    if (i < (long)MTOK * Dm) out[i] = hin[i];
}

// ---------------- host launcher ----------------
extern "C" void kernel_launch(void* const* d_in, const int* in_sizes, int n_in,
                              void* d_out, int out_size) {
    const float* x    = (const float*)d_in[0];
    const float* Wp   = (const float*)d_in[1];
    const float* bp   = (const float*)d_in[2];
    const float* pos  = (const float*)d_in[3];
    const float* ln1g = (const float*)d_in[4];
    const float* ln1b = (const float*)d_in[5];
    const float* Wq   = (const float*)d_in[6];
    const float* bq   = (const float*)d_in[7];
    const float* Wk   = (const float*)d_in[8];
    const float* bk   = (const float*)d_in[9];
    const float* Wv   = (const float*)d_in[10];
    const float* bv   = (const float*)d_in[11];
    const float* ln2g = (const float*)d_in[12];
    const float* ln2b = (const float*)d_in[13];
    const float* W1   = (const float*)d_in[14];
    const float* b1   = (const float*)d_in[15];
    const float* W2   = (const float*)d_in[16];
    const float* b2   = (const float*)d_in[17];

    __nv_bfloat16 *ph, *pl, *wph, *wpl, *wqh, *wql, *w1h, *w1l, *w2h, *w2l;
    __nv_bfloat16 *yh, *yl, *m1h, *m1l;
    float *bqkv, *h, *qkv, *S, *split;
    cudaGetSymbolAddress((void**)&ph,  g_patch_h);
    cudaGetSymbolAddress((void**)&pl,  g_patch_l);
    cudaGetSymbolAddress((void**)&wph, g_wp_h);
    cudaGetSymbolAddress((void**)&wpl, g_wp_l);
    cudaGetSymbolAddress((void**)&wqh, g_wqkv_h);
    cudaGetSymbolAddress((void**)&wql, g_wqkv_l);
    cudaGetSymbolAddress((void**)&w1h, g_w1_h);
    cudaGetSymbolAddress((void**)&w1l, g_w1_l);
    cudaGetSymbolAddress((void**)&w2h, g_w2_h);
    cudaGetSymbolAddress((void**)&w2l, g_w2_l);
    cudaGetSymbolAddress((void**)&yh,  g_y_h);
    cudaGetSymbolAddress((void**)&yl,  g_y_l);
    cudaGetSymbolAddress((void**)&m1h, g_m1_h);
    cudaGetSymbolAddress((void**)&m1l, g_m1_l);
    cudaGetSymbolAddress((void**)&bqkv, g_bqkv);
    cudaGetSymbolAddress((void**)&h,    g_h);
    cudaGetSymbolAddress((void**)&qkv,  g_qkv);
    cudaGetSymbolAddress((void**)&S,    g_S);
    cudaGetSymbolAddress((void**)&split, g_split);

    cudaFuncSetAttribute(gemm_mma<0>, cudaFuncAttributeMaxDynamicSharedMemorySize, GEMM_SMEM);
    cudaFuncSetAttribute(gemm_mma<2>, cudaFuncAttributeMaxDynamicSharedMemorySize, GEMM_SMEM);
    cudaFuncSetAttribute(gemm_mma<4>, cudaFuncAttributeMaxDynamicSharedMemorySize, GEMM_SMEM);

    // ---- prep: gather + weight conversion ----
    patch_gather<<<(int)(((long)MTOK * KP + 255) / 256), 256>>>(x);
    split_wp<<<(int)(((long)Dm * KP + 255) / 256), 256>>>(Wp);
    pack_qkv_split<<<dim3(HD / 32, Dm / 32, 3 * LAY * NH), dim3(32, 32)>>>(Wq, Wk, Wv);
    pack_bqkv<<<(LAY * QKVN + 255) / 256, 256>>>(bq, bk, bv);
    transpose_split<<<dim3(D4 / 32, Dm / 32, LAY), dim3(32, 32)>>>(W1, w1h, w1l, Dm, D4);
    transpose_split<<<dim3(Dm / 32, D4 / 32, LAY), dim3(32, 32)>>>(W2, w2h, w2l, D4, Dm);

    int nEl = (int)(((long)MTOK * Dm + 255) / 256);

    // ---- patch embed: split-K(4) + combine ----
    gemm_mma<4><<<dim3(Dm / 128, MTOK / 128, PSPLIT), 256, GEMM_SMEM>>>(
        ph, pl, wph, wpl, KP, KP / PSPLIT, MTOK, split, Dm, nullptr, nullptr, nullptr);
    combine_patch<<<nEl, 256>>>(split, bp, pos, h);

    for (int l = 0; l < LAY; l++) {
        layernorm_split<<<MTOK, 256>>>(h, yh, yl, ln1g + l * Dm, ln1b + l * Dm);
        gemm_mma<0><<<dim3(QKVN / 128, MTOK / 128), 256, GEMM_SMEM>>>(
            yh, yl, wqh + (long)l * QKVN * Dm, wql + (long)l * QKVN * Dm, Dm, Dm, MTOK,
            qkv, QKVN, bqkv + (long)l * QKVN, nullptr, nullptr);
        attn_qk<<<dim3(64, NH, BAT), 256>>>(qkv, S);
        softmax_k<<<BAT * NH * NTOK, 128>>>(S);
        attn_av<<<dim3(8, NH, BAT), 256>>>(S, qkv, h);
        layernorm_split<<<MTOK, 256>>>(h, yh, yl, ln2g + l * Dm, ln2b + l * Dm);
        gemm_mma<2><<<dim3(D4 / 128, MTOK / 128), 256, GEMM_SMEM>>>(
            yh, yl, w1h + (long)l * D4 * Dm, w1l + (long)l * D4 * Dm, Dm, Dm, MTOK,
            nullptr, D4, b1 + (long)l * D4, m1h, m1l);
        gemm_mma<4><<<dim3(Dm / 128, MTOK / 128, MSPLIT), 256, GEMM_SMEM>>>(
            m1h, m1l, w2h + (long)l * Dm * D4, w2l + (long)l * Dm * D4, D4, D4 / MSPLIT, MTOK,
            split, Dm, nullptr, nullptr, nullptr);
        combine_mlp2<<<nEl, 256>>>(split, b2 + (long)l * Dm, h);
    }
    copy_out<<<nEl, 256>>>(h, (float*)d_out);
}

// round 15
// speedup vs baseline: 1.0009x; 1.0009x over previous
#include <cuda_runtime.h>
#include <cuda_bf16.h>
#include <math.h>
#include <stdint.h>

// ---------------- problem dims ----------------
#define LAY 12
#define NH  12
#define Dm  768
#define HD  64
#define NTOK 512
#define BAT  4
#define MTOK (BAT*NTOK)     // 2048
#define KP   16384          // C*P^3
#define D4   3072
#define QKVN 2304
#define PSPLIT 4
#define MSPLIT 2

// ---------------- scratch (device globals; no allocs allowed) ----------------
__device__ __nv_bfloat16 g_patch_h[(size_t)MTOK * KP];
__device__ __nv_bfloat16 g_patch_l[(size_t)MTOK * KP];
__device__ __nv_bfloat16 g_wp_h[(size_t)Dm * KP];
__device__ __nv_bfloat16 g_wp_l[(size_t)Dm * KP];
__device__ __nv_bfloat16 g_wqkv_h[(size_t)LAY * QKVN * Dm];
__device__ __nv_bfloat16 g_wqkv_l[(size_t)LAY * QKVN * Dm];
__device__ __nv_bfloat16 g_w1_h[(size_t)LAY * D4 * Dm];   // [l][3072][768]
__device__ __nv_bfloat16 g_w1_l[(size_t)LAY * D4 * Dm];
__device__ __nv_bfloat16 g_w2_h[(size_t)LAY * Dm * D4];   // [l][768][3072]
__device__ __nv_bfloat16 g_w2_l[(size_t)LAY * Dm * D4];
__device__ float g_bqkv[(size_t)LAY * QKVN];
__device__ float g_h[(size_t)MTOK * Dm];
__device__ __nv_bfloat16 g_y_h[(size_t)MTOK * Dm];
__device__ __nv_bfloat16 g_y_l[(size_t)MTOK * Dm];
__device__ float g_qkv[(size_t)MTOK * QKVN];
__device__ float g_S[(size_t)BAT * NH * NTOK * NTOK];
__device__ __nv_bfloat16 g_m1_h[(size_t)MTOK * D4];
__device__ __nv_bfloat16 g_m1_l[(size_t)MTOK * D4];
__device__ float g_split[(size_t)PSPLIT * MTOK * Dm];

// ---------------- helpers ----------------
__device__ __forceinline__ float gelu_f(float v) {
    float c = 0.7978845608028654f * (v + 0.044715f * v * v * v);
    return 0.5f * v * (1.0f + tanhf(c));
}
__device__ __forceinline__ void split2(float v, __nv_bfloat16* hi, __nv_bfloat16* lo) {
    __nv_bfloat16 h = __float2bfloat16(v);
    *hi = h;
    *lo = __float2bfloat16(v - __bfloat162float(h));
}
__device__ __forceinline__ uint32_t smem_u32(const void* p) {
    uint32_t a;
    asm("{ .reg .u64 t; cvta.to.shared.u64 t, %1; cvt.u32.u64 %0, t; }" : "=r"(a) : "l"(p));
    return a;
}
#define SWZ(o) ((o) ^ ((((unsigned)(o)) >> 3) & 0x70u))

__device__ __forceinline__ void cpasync16(uint32_t dst, const void* src) {
    asm volatile("cp.async.cg.shared.global [%0], [%1], 16;" :: "r"(dst), "l"(src) : "memory");
}
#define LDSM4(r, addr) \
    asm volatile("ldmatrix.sync.aligned.m8n8.x4.shared.b16 {%0,%1,%2,%3}, [%4];" \
        : "=r"((r)[0]),"=r"((r)[1]),"=r"((r)[2]),"=r"((r)[3]) : "r"(addr))
#define MMA16816(c, a, b0, b1) \
    asm volatile("mma.sync.aligned.m16n8k16.row.col.f32.bf16.bf16.f32 " \
        "{%0,%1,%2,%3}, {%4,%5,%6,%7}, {%8,%9}, {%0,%1,%2,%3};" \
        : "+f"((c)[0]),"+f"((c)[1]),"+f"((c)[2]),"+f"((c)[3]) \
        : "r"((a)[0]),"r"((a)[1]),"r"((a)[2]),"r"((a)[3]), "r"(b0),"r"(b1))

#define GEMM_SMEM (2 * 65536)

// ============ mma.sync bf16x3 GEMM: C[M,N] = (Ah+Al)[M,K] x (Bh+Bl)[N,K]^T ============
// CTA tile 128x128, Kstep 64, 2-stage cp.async pipeline, 8 warps (2x4), warp tile 64x32.
// MODE 0: C = acc + bias     MODE 2: split(gelu(acc+bias)) -> oh/ol     MODE 4: split-K raw partial
template<int MODE>
__global__ void __launch_bounds__(256, 1) gemm_mma(
    const __nv_bfloat16* __restrict__ Ah, const __nv_bfloat16* __restrict__ Al,
    const __nv_bfloat16* __restrict__ Bh, const __nv_bfloat16* __restrict__ Bl,
    int lda, int Klen, int M,
    float* __restrict__ C, int ldc, const float* __restrict__ bias,
    __nv_bfloat16* __restrict__ oh, __nv_bfloat16* __restrict__ ol)
{
    extern __shared__ char smem[];
    uint32_t sb = smem_u32(smem);
    int tid = threadIdx.x;
    int bm = blockIdx.y << 7, bn = blockIdx.x << 7;
    if (MODE == 4) {
        long ko = (long)blockIdx.z * Klen;
        Ah += ko; Al += ko; Bh += ko; Bl += ko;
        C += (long)blockIdx.z * (long)M * ldc;
    }

    const int nsteps = Klen >> 6;

    auto loadstep = [&](int s) {
        uint32_t buf = sb + (uint32_t)(s & 1) * 65536u;
        long k0 = (long)s << 6;
#pragma unroll
        for (int i = 0; i < 16; i++) {
            int t = tid + (i << 8);
            int which = t >> 10;          // 0:Ah 1:Al 2:Bh 3:Bl
            int r = (t >> 3) & 127;
            int c16 = t & 7;
            const __nv_bfloat16* src;
            if (which == 0)      src = Ah + (long)(bm + r) * lda + k0 + c16 * 8;
            else if (which == 1) src = Al + (long)(bm + r) * lda + k0 + c16 * 8;
            else if (which == 2) src = Bh + (long)(bn + r) * lda + k0 + c16 * 8;
            else                 src = Bl + (long)(bn + r) * lda + k0 + c16 * 8;
            cpasync16(buf + (uint32_t)which * 16384u + SWZ(r * 128 + c16 * 16), src);
        }
        asm volatile("cp.async.commit_group;" ::: "memory");
    };

    loadstep(0);
    loadstep(1);

    int wid = tid >> 5, l = tid & 31;
    int wm = wid >> 2, wn = wid & 3;          // 2 x 4 warps

    // per-lane ldmatrix offsets (within 16KB tile, before swizzle)
    int aOff0 = (wm * 64 + (l & 15)) * 128 + ((l >> 4) << 4);          // + mf*2048 + k16*32
    int bOff0 = (wn * 32 + ((l >> 4) << 3) + (l & 7)) * 128 + (((l >> 3) & 1) << 4); // + nfp*2048 + k16*32

    float acc[4][4][4];
#pragma unroll
    for (int a = 0; a < 4; a++)
#pragma unroll
        for (int b = 0; b < 4; b++)
#pragma unroll
            for (int c = 0; c < 4; c++) acc[a][b][c] = 0.f;

    for (int s = 0; s < nsteps; s++) {
        if (s + 1 < nsteps) asm volatile("cp.async.wait_group 1;" ::: "memory");
        else                asm volatile("cp.async.wait_group 0;" ::: "memory");
        __syncthreads();
        uint32_t buf = sb + (uint32_t)(s & 1) * 65536u;
#pragma unroll
        for (int k16 = 0; k16 < 4; k16++) {
            uint32_t ah[4][4], al[4][4], bb[2][4];
            int kb = k16 << 5;
#pragma unroll
            for (int mf = 0; mf < 4; mf++) {
                int o = aOff0 + mf * 2048 + kb;
                LDSM4(ah[mf], buf + SWZ(o));
                LDSM4(al[mf], buf + 16384u + SWZ(o));
            }
#pragma unroll
            for (int p = 0; p < 2; p++)
                LDSM4(bb[p], buf + 32768u + SWZ(bOff0 + p * 2048 + kb));
#pragma unroll
            for (int mf = 0; mf < 4; mf++)
#pragma unroll
                for (int nf = 0; nf < 4; nf++) {
                    MMA16816(acc[mf][nf], ah[mf], bb[nf >> 1][(nf & 1) * 2], bb[nf >> 1][(nf & 1) * 2 + 1]);
                    MMA16816(acc[mf][nf], al[mf], bb[nf >> 1][(nf & 1) * 2], bb[nf >> 1][(nf & 1) * 2 + 1]);
                }
#pragma unroll
            for (int p = 0; p < 2; p++)
                LDSM4(bb[p], buf + 49152u + SWZ(bOff0 + p * 2048 + kb));
#pragma unroll
            for (int mf = 0; mf < 4; mf++)
#pragma unroll
                for (int nf = 0; nf < 4; nf++)
                    MMA16816(acc[mf][nf], ah[mf], bb[nf >> 1][(nf & 1) * 2], bb[nf >> 1][(nf & 1) * 2 + 1]);
        }
        __syncthreads();
        if (s + 2 < nsteps) loadstep(s + 2);
    }

    // ---------------- epilogue: direct register -> gmem ----------------
#pragma unroll
    for (int mf = 0; mf < 4; mf++)
#pragma unroll
        for (int nf = 0; nf < 4; nf++) {
            int gr = bm + wm * 64 + mf * 16 + (l >> 2);
            int gc = bn + wn * 32 + nf * 8 + (l & 3) * 2;
#pragma unroll
            for (int hrow = 0; hrow < 2; hrow++) {
                long go = (long)(gr + hrow * 8) * ldc + gc;
                float v0 = acc[mf][nf][hrow * 2 + 0];
                float v1 = acc[mf][nf][hrow * 2 + 1];
                if (MODE == 0) {
                    float2 r; r.x = v0 + bias[gc]; r.y = v1 + bias[gc + 1];
                    *reinterpret_cast<float2*>(C + go) = r;
                } else if (MODE == 2) {
                    float a0 = gelu_f(v0 + bias[gc]);
                    float a1 = gelu_f(v1 + bias[gc + 1]);
                    __nv_bfloat16 h0, l0, h1, l1;
                    split2(a0, &h0, &l0); split2(a1, &h1, &l1);
                    __nv_bfloat162 rh; rh.x = h0; rh.y = h1;
                    __nv_bfloat162 rl; rl.x = l0; rl.y = l1;
                    *reinterpret_cast<__nv_bfloat162*>(oh + go) = rh;
                    *reinterpret_cast<__nv_bfloat162*>(ol + go) = rl;
                } else {
                    float2 r; r.x = v0; r.y = v1;
                    *reinterpret_cast<float2*>(C + go) = r;
                }
            }
        }
}

// ---------------- combine kernels (split-K reductions + epilogues) ----------------
__global__ void __launch_bounds__(256) combine_patch(
    const float* __restrict__ parts, const float* __restrict__ bp,
    const float* __restrict__ pos, float* __restrict__ h) {
    long i = (long)blockIdx.x * 256 + threadIdx.x;
    if (i >= (long)MTOK * Dm) return;
    float s = 0.f;
#pragma unroll
    for (int z = 0; z < PSPLIT; z++) s += parts[(long)z * MTOK * Dm + i];
    int col = (int)(i % Dm);
    int n = (int)((i / Dm) & 511);
    h[i] = s + bp[col] + pos[(long)n * Dm + col];
}

__global__ void __launch_bounds__(256) combine_mlp2(
    const float* __restrict__ parts, const float* __restrict__ b2, float* __restrict__ h) {
    long i = (long)blockIdx.x * 256 + threadIdx.x;
    if (i >= (long)MTOK * Dm) return;
    h[i] += parts[i] + parts[(long)MTOK * Dm + i] + b2[i % Dm];
}

// ---------------- patch gather + split ----------------
__global__ void __launch_bounds__(256) patch_gather(const float* __restrict__ x) {
    long idx = (long)blockIdx.x * 256 + threadIdx.x;
    if (idx >= (long)MTOK * KP) return;
    int c = (int)(idx & (KP - 1));
    int m = (int)(idx >> 14);
    int b = m >> 9; int t = m & 511;
    int d = t >> 6, hh = (t >> 3) & 7, w = t & 7;
    int ch = c >> 12; int r = c & 4095;
    int i = r >> 8, j = (r >> 4) & 15, k = r & 15;
    long xi = ((((long)(b * 4 + ch) * 128 + (d * 16 + i)) * 128) + (hh * 16 + j)) * 128 + (w * 16 + k);
    split2(x[xi], &g_patch_h[idx], &g_patch_l[idx]);
}

__global__ void __launch_bounds__(256) split_wp(const float* __restrict__ wp) {
    long i = (long)blockIdx.x * 256 + threadIdx.x;
    if (i < (long)Dm * KP) split2(wp[i], &g_wp_h[i], &g_wp_l[i]);
}

// ---------------- qkv weight pack+transpose+split ----------------
__global__ void pack_qkv_split(const float* __restrict__ Wq, const float* __restrict__ Wk,
                               const float* __restrict__ Wv) {
    __shared__ float t[32][33];
    int z = blockIdx.z;
    int sel = z / (LAY * NH); int lh = z % (LAY * NH);
    int l = lh / NH, h = lh % NH;
    const float* W = (sel == 0) ? Wq : (sel == 1) ? Wk : Wv;
    const float* s = W + (((long)l * NH + h) * Dm) * HD;
    int d0 = blockIdx.y * 32, e0 = blockIdx.x * 32;
    t[threadIdx.y][threadIdx.x] = s[(long)(d0 + threadIdx.y) * HD + e0 + threadIdx.x];
    __syncthreads();
    int n = sel * Dm + h * HD + e0 + threadIdx.y;
    long o = ((long)l * QKVN + n) * Dm + d0 + threadIdx.x;
    split2(t[threadIdx.x][threadIdx.y], &g_wqkv_h[o], &g_wqkv_l[o]);
}
__global__ void __launch_bounds__(256) pack_bqkv(const float* __restrict__ bq,
                                                 const float* __restrict__ bk,
                                                 const float* __restrict__ bv) {
    int i = blockIdx.x * 256 + threadIdx.x;
    if (i >= LAY * QKVN) return;
    int l = i / QKVN, c = i % QKVN;
    int sel = c / Dm, cc = c % Dm;
    int h = cc >> 6, e = cc & 63;
    const float* b = (sel == 0) ? bq : (sel == 1) ? bk : bv;
    g_bqkv[i] = b[((long)l * NH + h) * HD + e];
}

// ---------------- generic transpose+split ----------------
__global__ void transpose_split(const float* __restrict__ src, __nv_bfloat16* __restrict__ dh,
                                __nv_bfloat16* __restrict__ dl, int R, int Cc) {
    __shared__ float t[32][33];
    int l = blockIdx.z;
    int r0 = blockIdx.y * 32, c0 = blockIdx.x * 32;
    const float* s = src + (long)l * R * Cc;
    t[threadIdx.y][threadIdx.x] = s[(long)(r0 + threadIdx.y) * Cc + c0 + threadIdx.x];
    __syncthreads();
    long o = (long)l * R * Cc + (long)(c0 + threadIdx.y) * R + r0 + threadIdx.x;
    split2(t[threadIdx.x][threadIdx.y], &dh[o], &dl[o]);
}

// ---------------- layernorm -> bf16 hi/lo ----------------
__global__ void __launch_bounds__(256) layernorm_split(
    const float* __restrict__ hin, __nv_bfloat16* __restrict__ yh, __nv_bfloat16* __restrict__ yl,
    const float* __restrict__ g, const float* __restrict__ b) {
    __shared__ float r1[8], r2[8];
    long base = (long)blockIdx.x * Dm;
    int t = threadIdx.x;
    float v0 = hin[base + t], v1 = hin[base + t + 256], v2 = hin[base + t + 512];
    float s = v0 + v1 + v2;
#pragma unroll
    for (int o = 16; o > 0; o >>= 1) s += __shfl_xor_sync(0xffffffffu, s, o);
    if ((t & 31) == 0) r1[t >> 5] = s;
    __syncthreads();
    float tot = r1[0] + r1[1] + r1[2] + r1[3] + r1[4] + r1[5] + r1[6] + r1[7];
    float mu = tot * (1.f / 768.f);
    float d0 = v0 - mu, d1 = v1 - mu, d2 = v2 - mu;
    float q = d0 * d0 + d1 * d1 + d2 * d2;
#pragma unroll
    for (int o = 16; o > 0; o >>= 1) q += __shfl_xor_sync(0xffffffffu, q, o);
    if ((t & 31) == 0) r2[t >> 5] = q;
    __syncthreads();
    float tot2 = r2[0] + r2[1] + r2[2] + r2[3] + r2[4] + r2[5] + r2[6] + r2[7];
    float inv = rsqrtf(tot2 * (1.f / 768.f) + 1e-5f);
    split2(d0 * inv * g[t]       + b[t],       &yh[base + t],       &yl[base + t]);
    split2(d1 * inv * g[t + 256] + b[t + 256], &yh[base + t + 256], &yl[base + t + 256]);
    split2(d2 * inv * g[t + 512] + b[t + 512], &yh[base + t + 512], &yl[base + t + 512]);
}

// ---------------- attention (fp32 SIMT) ----------------
__global__ void __launch_bounds__(256) attn_qk(const float* __restrict__ qkv, float* __restrict__ S) {
    __shared__ float qs[64][68];
    __shared__ float ks[64][68];
    int b = blockIdx.z, h = blockIdx.y;
    int mt = (blockIdx.x >> 3) * 64, nt = (blockIdx.x & 7) * 64;
    int tid = threadIdx.x;
    const float* qbase = qkv + (long)(b * 512 + mt) * QKVN + h * 64;
    const float* kbase = qkv + (long)(b * 512 + nt) * QKVN + 768 + h * 64;
#pragma unroll
    for (int s = 0; s < 4; s++) {
        int f = tid + 256 * s; int r = f >> 4; int c = (f & 15) * 4;
        *(float4*)&qs[r][c] = *(const float4*)(qbase + (long)r * QKVN + c);
        *(float4*)&ks[r][c] = *(const float4*)(kbase + (long)r * QKVN + c);
    }
    __syncthreads();
    int tx = tid & 15, ty = tid >> 4;
    float acc[4][4];
#pragma unroll
    for (int i = 0; i < 4; i++)
#pragma unroll
        for (int j = 0; j < 4; j++) acc[i][j] = 0.f;
#pragma unroll
    for (int e = 0; e < 64; e++) {
        float a[4], bb[4];
#pragma unroll
        for (int i = 0; i < 4; i++) a[i] = qs[ty * 4 + i][e];
#pragma unroll
        for (int j = 0; j < 4; j++) bb[j] = ks[tx * 4 + j][e];
#pragma unroll
        for (int i = 0; i < 4; i++)
#pragma unroll
            for (int j = 0; j < 4; j++) acc[i][j] = fmaf(a[i], bb[j], acc[i][j]);
    }
#pragma unroll
    for (int i = 0; i < 4; i++) {
        float4 r;
        r.x = acc[i][0] * 0.125f; r.y = acc[i][1] * 0.125f;
        r.z = acc[i][2] * 0.125f; r.w = acc[i][3] * 0.125f;
        *(float4*)(S + ((long)((b * NH + h) * 512 + mt + ty * 4 + i)) * 512 + nt + tx * 4) = r;
    }
}

__global__ void __launch_bounds__(128) softmax_k(float* __restrict__ S) {
    __shared__ float r1[4], r2[4];
    float* row = S + (long)blockIdx.x * 512;
    int t = threadIdx.x;
    float4 v = *(float4*)(row + t * 4);
    float mx = fmaxf(fmaxf(v.x, v.y), fmaxf(v.z, v.w));
#pragma unroll
    for (int o = 16; o > 0; o >>= 1) mx = fmaxf(mx, __shfl_xor_sync(0xffffffffu, mx, o));
    if ((t & 31) == 0) r1[t >> 5] = mx;
    __syncthreads();
    mx = fmaxf(fmaxf(r1[0], r1[1]), fmaxf(r1[2], r1[3]));
    v.x = __expf(v.x - mx); v.y = __expf(v.y - mx);
    v.z = __expf(v.z - mx); v.w = __expf(v.w - mx);
    float s = v.x + v.y + v.z + v.w;
#pragma unroll
    for (int o = 16; o > 0; o >>= 1) s += __shfl_xor_sync(0xffffffffu, s, o);
    if ((t & 31) == 0) r2[t >> 5] = s;
    __syncthreads();
    s = r2[0] + r2[1] + r2[2] + r2[3];
    float inv = 1.0f / s;
    v.x *= inv; v.y *= inv; v.z *= inv; v.w *= inv;
    *(float4*)(row + t * 4) = v;
}

__global__ void __launch_bounds__(256) attn_av(
    const float* __restrict__ S, const float* __restrict__ qkv, float* __restrict__ hio) {
    __shared__ float Ss[64][68];
    __shared__ float Vs[64][68];
    int b = blockIdx.z, h = blockIdx.y, mt = blockIdx.x * 64;
    int tid = threadIdx.x; int tx = tid & 15, ty = tid >> 4;
    const float* Sbase = S + ((long)(b * NH + h) * 512 + mt) * 512;
    const float* vbase = qkv + (long)(b * 512) * QKVN + 1536 + h * 64;
    float acc[4][4];
#pragma unroll
    for (int i = 0; i < 4; i++)
#pragma unroll
        for (int j = 0; j < 4; j++) acc[i][j] = 0.f;
    for (int k0 = 0; k0 < 512; k0 += 64) {
#pragma unroll
        for (int s = 0; s < 4; s++) {
            int f = tid + 256 * s; int r = f >> 4; int c = (f & 15) * 4;
            *(float4*)&Ss[r][c] = *(const float4*)(Sbase + (long)r * 512 + k0 + c);
            *(float4*)&Vs[r][c] = *(const float4*)(vbase + (long)(k0 + r) * QKVN + c);
        }
        __syncthreads();
#pragma unroll
        for (int kk = 0; kk < 64; kk++) {
            float a[4], bb[4];
#pragma unroll
            for (int i = 0; i < 4; i++) a[i] = Ss[ty * 4 + i][kk];
            *(float4*)&bb[0] = *(const float4*)&Vs[kk][tx * 4];
#pragma unroll
            for (int i = 0; i < 4; i++)
#pragma unroll
                for (int j = 0; j < 4; j++) acc[i][j] = fmaf(a[i], bb[j], acc[i][j]);
        }
        __syncthreads();
    }
#pragma unroll
    for (int i = 0; i < 4; i++) {
        long off = (long)(b * 512 + mt + ty * 4 + i) * Dm + h * 64 + tx * 4;
        float4 cur = *(float4*)(hio + off);
        cur.x += acc[i][0]; cur.y += acc[i][1];
        cur.z += acc[i][2]; cur.w += acc[i][3];
        *(float4*)(hio + off) = cur;
    }
}

__global__ void __launch_bounds__(256) copy_out(const float* __restrict__ hin, float* __restrict__ out) {
    long i = (long)blockIdx.x * 256 + threadIdx.x;
    if (i < (long)MTOK * Dm) out[i] = hin[i];
}

// ---------------- host launcher ----------------
extern "C" void kernel_launch(void* const* d_in, const int* in_sizes, int n_in,
                              void* d_out, int out_size) {
    const float* x    = (const float*)d_in[0];
    const float* Wp   = (const float*)d_in[1];
    const float* bp   = (const float*)d_in[2];
    const float* pos  = (const float*)d_in[3];
    const float* ln1g = (const float*)d_in[4];
    const float* ln1b = (const float*)d_in[5];
    const float* Wq   = (const float*)d_in[6];
    const float* bq   = (const float*)d_in[7];
    const float* Wk   = (const float*)d_in[8];
    const float* bk   = (const float*)d_in[9];
    const float* Wv   = (const float*)d_in[10];
    const float* bv   = (const float*)d_in[11];
    const float* ln2g = (const float*)d_in[12];
    const float* ln2b = (const float*)d_in[13];
    const float* W1   = (const float*)d_in[14];
    const float* b1   = (const float*)d_in[15];
    const float* W2   = (const float*)d_in[16];
    const float* b2   = (const float*)d_in[17];

    __nv_bfloat16 *ph, *pl, *wph, *wpl, *wqh, *wql, *w1h, *w1l, *w2h, *w2l;
    __nv_bfloat16 *yh, *yl, *m1h, *m1l;
    float *bqkv, *h, *qkv, *S, *split;
    cudaGetSymbolAddress((void**)&ph,  g_patch_h);
    cudaGetSymbolAddress((void**)&pl,  g_patch_l);
    cudaGetSymbolAddress((void**)&wph, g_wp_h);
    cudaGetSymbolAddress((void**)&wpl, g_wp_l);
    cudaGetSymbolAddress((void**)&wqh, g_wqkv_h);
    cudaGetSymbolAddress((void**)&wql, g_wqkv_l);
    cudaGetSymbolAddress((void**)&w1h, g_w1_h);
    cudaGetSymbolAddress((void**)&w1l, g_w1_l);
    cudaGetSymbolAddress((void**)&w2h, g_w2_h);
    cudaGetSymbolAddress((void**)&w2l, g_w2_l);
    cudaGetSymbolAddress((void**)&yh,  g_y_h);
    cudaGetSymbolAddress((void**)&yl,  g_y_l);
    cudaGetSymbolAddress((void**)&m1h, g_m1_h);
    cudaGetSymbolAddress((void**)&m1l, g_m1_l);
    cudaGetSymbolAddress((void**)&bqkv, g_bqkv);
    cudaGetSymbolAddress((void**)&h,    g_h);
    cudaGetSymbolAddress((void**)&qkv,  g_qkv);
    cudaGetSymbolAddress((void**)&S,    g_S);
    cudaGetSymbolAddress((void**)&split, g_split);

    cudaFuncSetAttribute(gemm_mma<0>, cudaFuncAttributeMaxDynamicSharedMemorySize, GEMM_SMEM);
    cudaFuncSetAttribute(gemm_mma<2>, cudaFuncAttributeMaxDynamicSharedMemorySize, GEMM_SMEM);
    cudaFuncSetAttribute(gemm_mma<4>, cudaFuncAttributeMaxDynamicSharedMemorySize, GEMM_SMEM);

    // ---- prep: gather + weight conversion ----
    patch_gather<<<(int)(((long)MTOK * KP + 255) / 256), 256>>>(x);
    split_wp<<<(int)(((long)Dm * KP + 255) / 256), 256>>>(Wp);
    pack_qkv_split<<<dim3(HD / 32, Dm / 32, 3 * LAY * NH), dim3(32, 32)>>>(Wq, Wk, Wv);
    pack_bqkv<<<(LAY * QKVN + 255) / 256, 256>>>(bq, bk, bv);
    transpose_split<<<dim3(D4 / 32, Dm / 32, LAY), dim3(32, 32)>>>(W1, w1h, w1l, Dm, D4);
    transpose_split<<<dim3(Dm / 32, D4 / 32, LAY), dim3(32, 32)>>>(W2, w2h, w2l, D4, Dm);

    int nEl = (int)(((long)MTOK * Dm + 255) / 256);

    // ---- patch embed: split-K(4) + combine ----
    gemm_mma<4><<<dim3(Dm / 128, MTOK / 128, PSPLIT), 256, GEMM_SMEM>>>(
        ph, pl, wph, wpl, KP, KP / PSPLIT, MTOK, split, Dm, nullptr, nullptr, nullptr);
    combine_patch<<<nEl, 256>>>(split, bp, pos, h);

    for (int l = 0; l < LAY; l++) {
        layernorm_split<<<MTOK, 256>>>(h, yh, yl, ln1g + l * Dm, ln1b + l * Dm);
        gemm_mma<0><<<dim3(QKVN / 128, MTOK / 128), 256, GEMM_SMEM>>>(
            yh, yl, wqh + (long)l * QKVN * Dm, wql + (long)l * QKVN * Dm, Dm, Dm, MTOK,
            qkv, QKVN, bqkv + (long)l * QKVN, nullptr, nullptr);
        attn_qk<<<dim3(64, NH, BAT), 256>>>(qkv, S);
        softmax_k<<<BAT * NH * NTOK, 128>>>(S);
        attn_av<<<dim3(8, NH, BAT), 256>>>(S, qkv, h);
        layernorm_split<<<MTOK, 256>>>(h, yh, yl, ln2g + l * Dm, ln2b + l * Dm);
        gemm_mma<2><<<dim3(D4 / 128, MTOK / 128), 256, GEMM_SMEM>>>(
            yh, yl, w1h + (long)l * D4 * Dm, w1l + (long)l * D4 * Dm, Dm, Dm, MTOK,
            nullptr, D4, b1 + (long)l * D4, m1h, m1l);
        gemm_mma<4><<<dim3(Dm / 128, MTOK / 128, MSPLIT), 256, GEMM_SMEM>>>(
            m1h, m1l, w2h + (long)l * Dm * D4, w2l + (long)l * Dm * D4, D4, D4 / MSPLIT, MTOK,
            split, Dm, nullptr, nullptr, nullptr);
        combine_mlp2<<<nEl, 256>>>(split, b2 + (long)l * Dm, h);
    }
    copy_out<<<nEl, 256>>>(h, (float*)d_out);
}